// round 3
// baseline (speedup 1.0000x reference)
#include <cuda_runtime.h>
#include <math.h>

// Problem constants (fixed shapes)
#define NS 512
#define NO 64
#define NT 2048
#define SO (NS*NO)          // 32768
#define HALF_T 1024

// ---------------------------------------------------------------------------
// Device scratch (allocation-free rule: __device__ globals)
// ---------------------------------------------------------------------------
// Per-step affine coefficients: for k=0: {P0, Ra(f0), Rb(f1), Rc(f2)};
// for k>=1: {P, R1(f[2k+1]), R2(f[2k+2]), 0}
__device__ float4 g_coef[2047 * NO];          // ~2 MB, L2-hot
// Tail reconstruction: h_t = alpha*h_1023 + beta*f_c for t in [1024,2047]
__device__ float2 g_tail[HALF_T * NO];        // 512 KB
__device__ float  g_nr[NO];                   // softplus(raw_noise)
__device__ float  g_fc[SO];                   // f[s,o,2047] compacted
__device__ float  g_h[(size_t)HALF_T * SO];   // h samples for t=0..1023 (134 MB)

// ---------------------------------------------------------------------------
// Kernel 1: per-(step k, output o) RK4 affine coefficients, fp64 internally.
//   dh = -a*ft + g(t)*h,  g(t) = b*sin(c*t*pi)
//   h' = P*h + sum_i QAi * A_i,  A_i = -a*ft_i
// ---------------------------------------------------------------------------
__global__ void coefA(const float* __restrict__ t,
                      const float* __restrict__ ra, const float* __restrict__ rb,
                      const float* __restrict__ rc, const float* __restrict__ rn) {
    int k = blockIdx.x;        // 0..2046
    int o = threadIdx.x;       // 0..63

    double t0 = (double)t[k];
    double t1 = (double)t[k + 1];
    double dt = t1 - t0;
    double e  = 0.5 * dt;
    double tm = t0 + e;

    double a = 1e-4 + (1.0 - 1e-4) / (1.0 + exp(-(double)ra[o]));
    double b = 1e-3 + (1.0 - 1e-3) / (1.0 + exp(-(double)rb[o]));
    double c = 1e-3 + (1.0 - 1e-3) / (1.0 + exp(-(double)rc[o]));

    const double PI_ = 3.14159265358979323846;
    double g1 = b * sin(c * t0 * PI_);
    double gm = b * sin(c * tm * PI_);
    double g4 = b * sin(c * t1 * PI_);

    // h-coefficients of the 4 stages
    double k1h = g1;
    double k2h = gm * (1.0 + e * k1h);
    double k3h = gm * (1.0 + e * k2h);
    double k4h = g4 * (1.0 + dt * k3h);
    double w   = dt / 6.0;
    double P   = 1.0 + w * (k1h + 2.0 * k2h + 2.0 * k3h + k4h);

    // forcing coefficients (A_i = -a * f_{idx_i})
    double ge  = gm * e;
    double QA1 = w * (1.0 + 2.0 * ge + 2.0 * ge * ge + g4 * dt * ge * ge);
    double QA2 = w * (2.0 + 2.0 * ge + g4 * dt * ge);
    double QA3 = w * (2.0 + g4 * dt);
    double QA4 = w;

    float4 out;
    if (k == 0) {
        // step 0 forcing indices: (0,1,2,2)
        out = make_float4((float)P, (float)(-a * QA1), (float)(-a * QA2),
                          (float)(-a * (QA3 + QA4)));
    } else {
        // step k>=1 forcing indices: (2k+1,2k+1,2k+2,2k+2)
        out = make_float4((float)P, (float)(-a * (QA1 + QA2)),
                          (float)(-a * (QA3 + QA4)), 0.0f);
    }
    g_coef[k * NO + o] = out;

    if (k == 0) {
        double x = (double)rn[o];
        g_nr[o] = (float)((x > 30.0) ? x : log1p(exp(x)));   // softplus
    }
}

// ---------------------------------------------------------------------------
// Kernel 2: segmented affine scan over steps 1023..2046 (constant forcing):
//   h_{k+1} = P*h_k + R*f_c  =>  h_t = alpha_t*h_1023 + beta_t*f_c
// One block per o; 64 threads x 16 steps each; exclusive-prefix combine.
// ---------------------------------------------------------------------------
__global__ void __launch_bounds__(64) coefB() {
    int o = blockIdx.x;      // 0..63
    int i = threadIdx.x;     // 0..63 (segment index)

    float A = 1.0f, B = 0.0f;
    float2 loc[16];
#pragma unroll
    for (int j = 0; j < 16; j++) {
        int k = 1023 + i * 16 + j;
        float4 cc = g_coef[k * NO + o];
        float P = cc.x;
        float R = cc.y + cc.z;
        B = fmaf(P, B, R);
        A = P * A;
        loc[j] = make_float2(A, B);
    }

    __shared__ float2 seg[64];
    seg[i] = make_float2(A, B);
    __syncthreads();
    if (i == 0) {
        float pA = 1.0f, pB = 0.0f;
        for (int s = 0; s < 64; s++) {
            float2 ts = seg[s];
            seg[s] = make_float2(pA, pB);                 // exclusive prefix
            pB = fmaf(ts.x, pB, ts.y);                    // compose(local, prefix)
            pA = ts.x * pA;
        }
    }
    __syncthreads();
    float2 p = seg[i];
#pragma unroll
    for (int j = 0; j < 16; j++) {
        float Ag = loc[j].x * p.x;
        float Bg = fmaf(loc[j].x, p.y, loc[j].y);
        g_tail[(i * 16 + j) * NO + o] = make_float2(Ag, Bg);   // t = 1024+16i+j
    }
}

// ---------------------------------------------------------------------------
// Kernel 3: chains. One thread per (s,o). Runs steps 0..1022 (h_0..h_1023),
// stores g_h[t][s][o] (lanes over o => coalesced 128B stores), one float4
// f-load per 2 steps, coefficient float4 L1-hot (same o-pattern across the
// blocks resident on an SM).
// ---------------------------------------------------------------------------
__global__ void __launch_bounds__(64) chains(const float* __restrict__ f) {
    int o = threadIdx.x;      // 0..63
    int s = blockIdx.x;       // 0..511
    int base = s * NO + o;

    const float4* fq = (const float4*)(f + (size_t)base * NT);

    float h = 0.5f;
    g_h[base] = 0.5f;                       // t = 0

    float4 q  = fq[0];                      // f[0..3]
    float4 c0 = g_coef[o];                  // k = 0
    h = c0.x * h + c0.y * q.x + c0.z * q.y + c0.w * q.z;
    g_h[(size_t)SO + base] = h;             // t = 1
    float carry = q.w;                      // f[3]

#pragma unroll 4
    for (int j = 0; j < 511; j++) {
        float4 qq = fq[1 + j];              // f[4+4j .. 7+4j]
        int k = 2 * j + 1;
        float4 c1 = g_coef[k * NO + o];
        h = fmaf(c1.x, h, fmaf(c1.y, carry, c1.z * qq.x));   // step k: f[2k+1]=carry, f[2k+2]=qq.x
        g_h[(size_t)(k + 1) * SO + base] = h;
        float4 c2 = g_coef[(k + 1) * NO + o];
        h = fmaf(c2.x, h, fmaf(c2.y, qq.y, c2.z * qq.z));    // step k+1
        g_h[(size_t)(k + 2) * SO + base] = h;
        carry = qq.w;
    }
    // after j=510: carry = f[2047] (constant tail forcing)
    g_fc[base] = carry;
}

// ---------------------------------------------------------------------------
// Kernel 4: stats. One block per t. Single-pass shifted-moments mean/var over
// the 512 samples:
//   shift = h[s=0] + nr/2  (per (t,o), ~= noisy mean)
//   var = (Sum d^2 - (Sum d)^2/512) / 511,  d = h_noisy - shift
// For t>=1024 samples are reconstructed: h = alpha*h_1023 + beta*f_c (L2-hot).
// Tiny smem -> full occupancy for DRAM latency hiding.
// ---------------------------------------------------------------------------
__global__ void __launch_bounds__(256) stats(const float* __restrict__ u,
                                             float* __restrict__ out) {
    __shared__ float r0[4][NO], r1[4][NO], r2[4][NO];

    int t   = blockIdx.x;
    int tid = threadIdx.x;
    int o   = tid & 63;
    int ss  = tid >> 6;                     // 0..3

    float nr = g_nr[o];
    bool tail = (t >= HALF_T);
    float alpha = 1.0f, beta = 0.0f;
    if (tail) {
        float2 ab = g_tail[(t - HALF_T) * NO + o];
        alpha = ab.x; beta = ab.y;
    }
    const float* hrow = g_h + (size_t)(tail ? (HALF_T - 1) : t) * SO;
    const float* urow = u + (size_t)t * SO;

    // per-(t,o) shift near the noisy mean (exact algebra for any constant)
    float h0 = hrow[o];                         // sample s=0
    if (tail) h0 = fmaf(alpha, h0, beta * g_fc[o]);
    float shift = fmaf(nr, 0.5f, h0);

    float sh = 0.0f, sd = 0.0f, sq = 0.0f;
#pragma unroll 4
    for (int i = 0; i < 128; i++) {
        int idx = (i * 4 + ss) * NO + o;        // consecutive lanes -> contiguous
        float hv = hrow[idx];
        if (tail) hv = fmaf(alpha, hv, beta * g_fc[idx]);
        float d = fmaf(nr, urow[idx], hv) - shift;
        sh += hv;
        sd += d;
        sq = fmaf(d, d, sq);
    }
    r0[ss][o] = sh;
    r1[ss][o] = sd;
    r2[ss][o] = sq;
    __syncthreads();
    if (ss == 0) {
        float Sh = r0[0][o] + r0[1][o] + r0[2][o] + r0[3][o];
        float Sd = r1[0][o] + r1[1][o] + r1[2][o] + r1[3][o];
        float Sq = r2[0][o] + r2[1][o] + r2[2][o] + r2[3][o];
        out[t * NO + o]           = Sh * (1.0f / 512.0f);                        // mean
        out[NT * NO + t * NO + o] = (Sq - Sd * Sd * (1.0f / 512.0f))
                                    * (1.0f / 511.0f) + 1e-6f;                    // var
    }
}

// ---------------------------------------------------------------------------
// Launch
// ---------------------------------------------------------------------------
extern "C" void kernel_launch(void* const* d_in, const int* in_sizes, int n_in,
                              void* d_out, int out_size) {
    const float* t_  = (const float*)d_in[0];   // [T]
    const float* f_  = (const float*)d_in[1];   // [S,O,T]
    const float* ra_ = (const float*)d_in[2];   // [O,1]
    const float* rb_ = (const float*)d_in[3];
    const float* rc_ = (const float*)d_in[4];
    const float* rn_ = (const float*)d_in[5];
    const float* u_  = (const float*)d_in[6];   // [T,S,O]
    float* out = (float*)d_out;                 // [2,T,O]

    coefA<<<2047, NO>>>(t_, ra_, rb_, rc_, rn_);
    coefB<<<NO, 64>>>();
    chains<<<NS, NO>>>(f_);
    stats<<<NT, 256>>>(u_, out);
}

// round 4
// speedup vs baseline: 1.0843x; 1.0843x over previous
#include <cuda_runtime.h>
#include <cuda_fp16.h>
#include <math.h>

// Problem constants (fixed shapes)
#define NS 512
#define NO 64
#define NT 2048
#define SO (NS*NO)          // 32768
#define HALF_T 1024
#define TC 128              // time-chunk per smem stage in chains
#define FSTRIDE 133         // smem row stride (133 % 32 == 5, gcd(5,32)=1 -> conflict-free)

// ---------------------------------------------------------------------------
// Device scratch (allocation-free rule: __device__ globals)
// ---------------------------------------------------------------------------
__device__ __align__(16) float4 g_coef[2047 * NO];     // per-step affine coeffs
__device__ __align__(16) float  g_alpha[HALF_T * NO];  // tail: h_t = a*h_1023 + b*f_c
__device__ __align__(16) float  g_beta [HALF_T * NO];
__device__ __align__(16) float  g_nr[NO];              // softplus(raw_noise)
__device__ __align__(16) float  g_fc[SO];              // f[s,o,2047]
__device__ __half g_h[(size_t)HALF_T * SO];            // h for t=0..1023 (67 MB, fp16)

// ---------------------------------------------------------------------------
// Kernel 1: per-(step k, output o) RK4 affine coefficients, fp64 internally.
//   dh = -a*ft + g(t)*h,  g(t) = b*sin(c*t*pi)
// ---------------------------------------------------------------------------
__global__ void coefA(const float* __restrict__ t,
                      const float* __restrict__ ra, const float* __restrict__ rb,
                      const float* __restrict__ rc, const float* __restrict__ rn) {
    int k = blockIdx.x;        // 0..2046
    int o = threadIdx.x;       // 0..63

    double t0 = (double)t[k];
    double t1 = (double)t[k + 1];
    double dt = t1 - t0;
    double e  = 0.5 * dt;
    double tm = t0 + e;

    double a = 1e-4 + (1.0 - 1e-4) / (1.0 + exp(-(double)ra[o]));
    double b = 1e-3 + (1.0 - 1e-3) / (1.0 + exp(-(double)rb[o]));
    double c = 1e-3 + (1.0 - 1e-3) / (1.0 + exp(-(double)rc[o]));

    const double PI_ = 3.14159265358979323846;
    double g1 = b * sin(c * t0 * PI_);
    double gm = b * sin(c * tm * PI_);
    double g4 = b * sin(c * t1 * PI_);

    double k1h = g1;
    double k2h = gm * (1.0 + e * k1h);
    double k3h = gm * (1.0 + e * k2h);
    double k4h = g4 * (1.0 + dt * k3h);
    double w   = dt / 6.0;
    double P   = 1.0 + w * (k1h + 2.0 * k2h + 2.0 * k3h + k4h);

    double ge  = gm * e;
    double QA1 = w * (1.0 + 2.0 * ge + 2.0 * ge * ge + g4 * dt * ge * ge);
    double QA2 = w * (2.0 + 2.0 * ge + g4 * dt * ge);
    double QA3 = w * (2.0 + g4 * dt);
    double QA4 = w;

    float4 out;
    if (k == 0) {
        // step 0 forcing indices: (0,1,2,2)
        out = make_float4((float)P, (float)(-a * QA1), (float)(-a * QA2),
                          (float)(-a * (QA3 + QA4)));
    } else {
        // step k>=1 forcing indices: (2k+1,2k+1,2k+2,2k+2)
        out = make_float4((float)P, (float)(-a * (QA1 + QA2)),
                          (float)(-a * (QA3 + QA4)), 0.0f);
    }
    g_coef[k * NO + o] = out;

    if (k == 0) {
        double x = (double)rn[o];
        g_nr[o] = (float)((x > 30.0) ? x : log1p(exp(x)));   // softplus
    }
}

// ---------------------------------------------------------------------------
// Kernel 2: segmented affine scan over steps 1023..2046 (constant forcing):
//   h_t = alpha_t*h_1023 + beta_t*f_c ; one block per o, 64x16 segmented scan
// ---------------------------------------------------------------------------
__global__ void __launch_bounds__(64) coefB() {
    int o = blockIdx.x;      // 0..63
    int i = threadIdx.x;     // 0..63 (segment index)

    float A = 1.0f, B = 0.0f;
    float2 loc[16];
#pragma unroll
    for (int j = 0; j < 16; j++) {
        int k = 1023 + i * 16 + j;
        float4 cc = g_coef[k * NO + o];
        float P = cc.x;
        float R = cc.y + cc.z;
        B = fmaf(P, B, R);
        A = P * A;
        loc[j] = make_float2(A, B);
    }

    __shared__ float2 seg[64];
    seg[i] = make_float2(A, B);
    __syncthreads();
    if (i == 0) {
        float pA = 1.0f, pB = 0.0f;
        for (int s = 0; s < 64; s++) {
            float2 ts = seg[s];
            seg[s] = make_float2(pA, pB);                 // exclusive prefix
            pB = fmaf(ts.x, pB, ts.y);
            pA = ts.x * pA;
        }
    }
    __syncthreads();
    float2 p = seg[i];
#pragma unroll
    for (int j = 0; j < 16; j++) {
        int idx = (i * 16 + j) * NO + o;                  // t = 1024+16i+j
        g_alpha[idx] = loc[j].x * p.x;
        g_beta[idx]  = fmaf(loc[j].x, p.y, loc[j].y);
    }
}

// ---------------------------------------------------------------------------
// Kernel 3: chains v2. One block per sample s (128 threads). The 64 f-rows of
// this sample are staged chunk-by-chunk (128 t) through smem with fully
// coalesced global loads; 64 threads (one per o) advance the recurrence from
// smem (stride-133 rows -> conflict-free LDS). h stored fp16, coalesced.
// ---------------------------------------------------------------------------
__global__ void __launch_bounds__(128) chains(const float* __restrict__ f) {
    __shared__ float F[NO * FSTRIDE];     // 64*133*4 = 34048 B
    int tid = threadIdx.x;
    int s = blockIdx.x;
    int o = tid;                          // compute role if tid < 64
    const float* fbase = f + (size_t)s * NO * NT;

    float h = 0.5f, carry = 0.0f;
    int kbase = 0;

    for (int m = 0; m < NT / TC; m++) {
        __syncthreads();                  // previous chunk fully consumed
        {
            int c  = tid & 31;            // float4 index within row
            int wr = tid >> 5;            // warp id 0..3
#pragma unroll
            for (int it = 0; it < 16; it++) {
                int row = it * 4 + wr;
                float4 v = *(const float4*)(fbase + (size_t)row * NT + m * TC + c * 4);
                float* dst = &F[row * FSTRIDE + c * 4];
                dst[0] = v.x; dst[1] = v.y; dst[2] = v.z; dst[3] = v.w;
            }
        }
        __syncthreads();
        if (tid < 64) {
            const float* Fr = &F[o * FSTRIDE];
            size_t base = (size_t)s * NO + o;
            if (m == 0) {
                g_h[base] = __float2half(0.5f);                       // t = 0
                float4 c0 = g_coef[o];                                // step 0: f(0,1,2)
                h = c0.x * 0.5f + c0.y * Fr[0] + c0.z * Fr[1] + c0.w * Fr[2];
                g_h[(size_t)SO + base] = __float2half(h);             // t = 1
#pragma unroll 8
                for (int j = 0; j < 62; j++) {                        // steps 1..62
                    int k = 1 + j;
                    float4 cc = g_coef[k * NO + o];
                    h = fmaf(cc.x, h, fmaf(cc.y, Fr[3 + 2 * j], cc.z * Fr[4 + 2 * j]));
                    g_h[(size_t)(k + 1) * SO + base] = __float2half(h);
                }
                carry = Fr[TC - 1];                                   // f[127]
                kbase = 63;
            } else {
                // pending step kbase: f[2k+1] = carry, f[2k+2] = Fr[0]
                float4 cc = g_coef[kbase * NO + o];
                h = fmaf(cc.x, h, fmaf(cc.y, carry, cc.z * Fr[0]));
                g_h[(size_t)(kbase + 1) * SO + base] = __float2half(h);
#pragma unroll 8
                for (int j = 0; j < 63; j++) {                        // 63 in-chunk steps
                    int k = kbase + 1 + j;
                    float4 c2 = g_coef[k * NO + o];
                    h = fmaf(c2.x, h, fmaf(c2.y, Fr[1 + 2 * j], c2.z * Fr[2 + 2 * j]));
                    g_h[(size_t)(k + 1) * SO + base] = __float2half(h);
                }
                carry = Fr[TC - 1];
                kbase += 64;
            }
        }
    }
    // after m=15: kbase=1023, steps 0..1022 done, carry = f[2047]
    if (tid < 64) g_fc[(size_t)s * NO + o] = carry;
}

// ---------------------------------------------------------------------------
// Kernel 4: stats. One block per t; thread = (o-quad, s-slice). Single-pass
// shifted-moments mean/var (shift = h[s=0]+nr/2, exact algebra), float4 u
// loads + half4 h loads. Tail t reconstructs h from (alpha,beta,f_c), L2-hot.
// ---------------------------------------------------------------------------
__global__ void __launch_bounds__(256) stats(const float* __restrict__ u,
                                             float* __restrict__ out) {
    __shared__ float4 R0[16][16], R1[16][16], R2[16][16];

    int t   = blockIdx.x;
    int tid = threadIdx.x;
    int q   = tid & 15;                   // o-quad: o = 4q..4q+3
    int ss  = tid >> 4;                   // s-slice 0..15

    bool tail = (t >= HALF_T);
    float4 nr4 = *(const float4*)&g_nr[q * 4];
    float4 al = make_float4(1.f, 1.f, 1.f, 1.f);
    float4 be = make_float4(0.f, 0.f, 0.f, 0.f);
    if (tail) {
        al = *(const float4*)&g_alpha[(t - HALF_T) * NO + q * 4];
        be = *(const float4*)&g_beta [(t - HALF_T) * NO + q * 4];
    }
    const __half* hrow = g_h + (size_t)(tail ? (HALF_T - 1) : t) * SO;
    const float*  urow = u + (size_t)t * SO;

    // shift per (t, o): sample s=0 value + nr/2 (~= noisy mean; exact algebra)
    float4 h0;
    {
        uint2 hb = *(const uint2*)(hrow + q * 4);
        __half2 p0 = *reinterpret_cast<const __half2*>(&hb.x);
        __half2 p1 = *reinterpret_cast<const __half2*>(&hb.y);
        float2 f0 = __half22float2(p0), f1 = __half22float2(p1);
        h0 = make_float4(f0.x, f0.y, f1.x, f1.y);
    }
    if (tail) {
        float4 fc0 = *(const float4*)&g_fc[q * 4];
        h0.x = fmaf(al.x, h0.x, be.x * fc0.x);
        h0.y = fmaf(al.y, h0.y, be.y * fc0.y);
        h0.z = fmaf(al.z, h0.z, be.z * fc0.z);
        h0.w = fmaf(al.w, h0.w, be.w * fc0.w);
    }
    float4 shift = make_float4(fmaf(nr4.x, 0.5f, h0.x), fmaf(nr4.y, 0.5f, h0.y),
                               fmaf(nr4.z, 0.5f, h0.z), fmaf(nr4.w, 0.5f, h0.w));

    float4 sh = make_float4(0.f, 0.f, 0.f, 0.f);
    float4 sd = sh, sq = sh;
#pragma unroll 4
    for (int i = 0; i < 32; i++) {
        int idx = (i * 16 + ss) * NO + q * 4;
        uint2 hb = *(const uint2*)(hrow + idx);
        __half2 p0 = *reinterpret_cast<const __half2*>(&hb.x);
        __half2 p1 = *reinterpret_cast<const __half2*>(&hb.y);
        float2 f0 = __half22float2(p0), f1 = __half22float2(p1);
        float4 hv = make_float4(f0.x, f0.y, f1.x, f1.y);
        if (tail) {
            float4 fc = *(const float4*)&g_fc[idx];
            hv.x = fmaf(al.x, hv.x, be.x * fc.x);
            hv.y = fmaf(al.y, hv.y, be.y * fc.y);
            hv.z = fmaf(al.z, hv.z, be.z * fc.z);
            hv.w = fmaf(al.w, hv.w, be.w * fc.w);
        }
        float4 uv = *(const float4*)&urow[idx];
        float4 d = make_float4(fmaf(nr4.x, uv.x, hv.x) - shift.x,
                               fmaf(nr4.y, uv.y, hv.y) - shift.y,
                               fmaf(nr4.z, uv.z, hv.z) - shift.z,
                               fmaf(nr4.w, uv.w, hv.w) - shift.w);
        sh.x += hv.x; sh.y += hv.y; sh.z += hv.z; sh.w += hv.w;
        sd.x += d.x;  sd.y += d.y;  sd.z += d.z;  sd.w += d.w;
        sq.x = fmaf(d.x, d.x, sq.x); sq.y = fmaf(d.y, d.y, sq.y);
        sq.z = fmaf(d.z, d.z, sq.z); sq.w = fmaf(d.w, d.w, sq.w);
    }
    R0[ss][q] = sh; R1[ss][q] = sd; R2[ss][q] = sq;
    __syncthreads();
    if (tid < 16) {
        float4 Sh = make_float4(0.f, 0.f, 0.f, 0.f);
        float4 Sd = Sh, Sq = Sh;
#pragma unroll
        for (int j = 0; j < 16; j++) {
            float4 a0 = R0[j][tid], a1 = R1[j][tid], a2 = R2[j][tid];
            Sh.x += a0.x; Sh.y += a0.y; Sh.z += a0.z; Sh.w += a0.w;
            Sd.x += a1.x; Sd.y += a1.y; Sd.z += a1.z; Sd.w += a1.w;
            Sq.x += a2.x; Sq.y += a2.y; Sq.z += a2.z; Sq.w += a2.w;
        }
        const float i512 = 1.0f / 512.0f, i511 = 1.0f / 511.0f;
        float4 mean = make_float4(Sh.x * i512, Sh.y * i512, Sh.z * i512, Sh.w * i512);
        float4 var  = make_float4((Sq.x - Sd.x * Sd.x * i512) * i511 + 1e-6f,
                                  (Sq.y - Sd.y * Sd.y * i512) * i511 + 1e-6f,
                                  (Sq.z - Sd.z * Sd.z * i512) * i511 + 1e-6f,
                                  (Sq.w - Sd.w * Sd.w * i512) * i511 + 1e-6f);
        *(float4*)&out[t * NO + tid * 4]           = mean;   // [0,t,o]
        *(float4*)&out[NT * NO + t * NO + tid * 4] = var;    // [1,t,o]
    }
}

// ---------------------------------------------------------------------------
// Launch
// ---------------------------------------------------------------------------
extern "C" void kernel_launch(void* const* d_in, const int* in_sizes, int n_in,
                              void* d_out, int out_size) {
    const float* t_  = (const float*)d_in[0];   // [T]
    const float* f_  = (const float*)d_in[1];   // [S,O,T]
    const float* ra_ = (const float*)d_in[2];   // [O,1]
    const float* rb_ = (const float*)d_in[3];
    const float* rc_ = (const float*)d_in[4];
    const float* rn_ = (const float*)d_in[5];
    const float* u_  = (const float*)d_in[6];   // [T,S,O]
    float* out = (float*)d_out;                 // [2,T,O]

    coefA<<<2047, NO>>>(t_, ra_, rb_, rc_, rn_);
    coefB<<<NO, 64>>>();
    chains<<<NS, 128>>>(f_);
    stats<<<NT, 256>>>(u_, out);
}

// round 5
// speedup vs baseline: 1.2652x; 1.1668x over previous
#include <cuda_runtime.h>
#include <cuda_fp16.h>
#include <math.h>

// Problem constants (fixed shapes)
#define NS 512
#define NO 64
#define NT 2048
#define SO (NS*NO)          // 32768
#define HALF_T 1024

// chains v3 tiling
#define SPB 4               // samples per block
#define CT 64               // time points per chunk
#define SPC 32              // steps per chunk
#define NCHUNK (NT/CT)      // 32
#define FSTR 65             // smem row stride (odd -> conflict-free scalar LDS)
#define CH_SMEM ((SPB*NO*FSTR)*4 + SPC*NO*16)   // 66560 + 32768 = 99328 B

// ---------------------------------------------------------------------------
// Device scratch (allocation-free rule: __device__ globals)
// ---------------------------------------------------------------------------
__device__ __align__(16) float4 g_coef[2047 * NO];     // per-step affine coeffs
__device__ __align__(16) float  g_alpha[HALF_T * NO];  // tail: h_t = a*h_1023 + b*f_c
__device__ __align__(16) float  g_beta [HALF_T * NO];
__device__ __align__(16) float  g_nr[NO];              // softplus(raw_noise)
__device__ __align__(16) float  g_fc[SO];              // f[s,o,2047]
__device__ __half g_h[(size_t)HALF_T * SO];            // h for t=0..1023 (67 MB, fp16)

// ---------------------------------------------------------------------------
// Kernel 1: RK4 affine coefficients, fp32 (fp64 only for sin-phase reduction).
//   dh = -a*ft + g(t)*h,  g(t) = b*sin(c*t*pi)
//   h' = P*h + sum_i QAi * A_i,  A_i = -a*ft_i
// ---------------------------------------------------------------------------
__device__ __forceinline__ float sin_pi_ct(float c, float tv) {
    // sin(pi * c * t): compute c*t in fp64, reduce mod 2, evaluate sinpif.
    double ph = (double)c * (double)tv;
    double r  = ph - 2.0 * floor(ph * 0.5);      // [0,2)
    return sinpif((float)r);
}

__global__ void coefA(const float* __restrict__ t,
                      const float* __restrict__ ra, const float* __restrict__ rb,
                      const float* __restrict__ rc, const float* __restrict__ rn) {
    int k = blockIdx.x;        // 0..2046
    int o = threadIdx.x;       // 0..63

    float t0 = t[k];
    float t1 = t[k + 1];
    float dt = t1 - t0;
    float e  = 0.5f * dt;
    float tm = t0 + e;

    float a = 1e-4f + (1.0f - 1e-4f) / (1.0f + expf(-ra[o]));
    float b = 1e-3f + (1.0f - 1e-3f) / (1.0f + expf(-rb[o]));
    float c = 1e-3f + (1.0f - 1e-3f) / (1.0f + expf(-rc[o]));

    float g1 = b * sin_pi_ct(c, t0);
    float gm = b * sin_pi_ct(c, tm);
    float g4 = b * sin_pi_ct(c, t1);

    float k1h = g1;
    float k2h = gm * (1.0f + e * k1h);
    float k3h = gm * (1.0f + e * k2h);
    float k4h = g4 * (1.0f + dt * k3h);
    float w   = dt * (1.0f / 6.0f);
    float P   = 1.0f + w * (k1h + 2.0f * k2h + 2.0f * k3h + k4h);

    float ge  = gm * e;
    float QA1 = w * (1.0f + 2.0f * ge + 2.0f * ge * ge + g4 * dt * ge * ge);
    float QA2 = w * (2.0f + 2.0f * ge + g4 * dt * ge);
    float QA3 = w * (2.0f + g4 * dt);
    float QA4 = w;

    float4 out;
    if (k == 0) {
        // step 0 forcing indices: (0,1,2,2)
        out = make_float4(P, -a * QA1, -a * QA2, -a * (QA3 + QA4));
    } else {
        // step k>=1 forcing indices: (2k+1,2k+1,2k+2,2k+2)
        out = make_float4(P, -a * (QA1 + QA2), -a * (QA3 + QA4), 0.0f);
    }
    g_coef[k * NO + o] = out;

    if (k == 0) {
        float x = rn[o];
        g_nr[o] = (x > 20.0f) ? x : log1pf(expf(x));   // softplus
    }
}

// ---------------------------------------------------------------------------
// Kernel 2: segmented affine scan over steps 1023..2046 (constant forcing):
//   h_t = alpha_t*h_1023 + beta_t*f_c ; one block per o, 64x16 segmented scan
// ---------------------------------------------------------------------------
__global__ void __launch_bounds__(64) coefB() {
    int o = blockIdx.x;      // 0..63
    int i = threadIdx.x;     // 0..63 (segment index)

    float A = 1.0f, B = 0.0f;
    float2 loc[16];
#pragma unroll
    for (int j = 0; j < 16; j++) {
        int k = 1023 + i * 16 + j;
        float4 cc = g_coef[k * NO + o];
        float P = cc.x;
        float R = cc.y + cc.z;
        B = fmaf(P, B, R);
        A = P * A;
        loc[j] = make_float2(A, B);
    }

    __shared__ float2 seg[64];
    seg[i] = make_float2(A, B);
    __syncthreads();
    if (i == 0) {
        float pA = 1.0f, pB = 0.0f;
        for (int s = 0; s < 64; s++) {
            float2 ts = seg[s];
            seg[s] = make_float2(pA, pB);                 // exclusive prefix
            pB = fmaf(ts.x, pB, ts.y);
            pA = ts.x * pA;
        }
    }
    __syncthreads();
    float2 p = seg[i];
#pragma unroll
    for (int j = 0; j < 16; j++) {
        int idx = (i * 16 + j) * NO + o;                  // t = 1024+16i+j
        g_alpha[idx] = loc[j].x * p.x;
        g_beta[idx]  = fmaf(loc[j].x, p.y, loc[j].y);
    }
}

// ---------------------------------------------------------------------------
// Kernel 3: chains v3. Block = 4 samples x 64 outputs (256 threads, all
// compute). Per 64-t chunk, BOTH the f tile and the 32-step coefficient slab
// are staged in smem with coalesced global loads; the serial RK4 loop then
// touches only smem (no global latency on the dependent chain). h stored
// fp16, coalesced [t][s][o].
// ---------------------------------------------------------------------------
__global__ void __launch_bounds__(256) chains(const float* __restrict__ f) {
    extern __shared__ float smem[];
    float*  Fs = smem;                                   // [SPB*NO][FSTR]
    float4* Cs = (float4*)(smem + SPB * NO * FSTR);      // [SPC][NO]

    int tid = threadIdx.x;
    int w   = tid >> 5;            // warp 0..7
    int l   = tid & 31;            // lane
    int s_base = blockIdx.x * SPB;

    int sl = tid >> 6;             // compute role: sample 0..3
    int o  = tid & 63;             //               output 0..63
    const float* Fr = &Fs[(sl * NO + o) * FSTR];
    int base = (s_base + sl) * NO + o;

    float h = 0.5f, carry = 0.0f;

    for (int m = 0; m < NCHUNK; m++) {
        // ---- load phase: F tile (256 rows x 64 t) + coef slab (32 steps) ----
#pragma unroll 8
        for (int i = 0; i < 32; i++) {
            int r  = i * 8 + w;                          // row = sl*64 + o
            int rs = r >> 6, ro = r & 63;
            float2 v = *(const float2*)(f + ((size_t)(s_base + rs) * NO + ro) * NT
                                          + m * CT + 2 * l);
            float* dst = &Fs[r * FSTR + 2 * l];
            dst[0] = v.x; dst[1] = v.y;
        }
        int kb = (m == 0) ? 0 : (SPC * m - 1);
#pragma unroll
        for (int i = 0; i < 8; i++) {
            int idx = i * 256 + tid;                     // idx = j*NO + o
            Cs[idx] = g_coef[(kb + (idx >> 6)) * NO + (idx & 63)];
        }
        __syncthreads();

        // ---- compute phase: 31-32 steps from smem only ----
        if (m == 0) {
            g_h[base] = __float2half(0.5f);                              // t=0
            float4 c0 = Cs[o];                                           // step 0
            h = c0.x * 0.5f + c0.y * Fr[0] + c0.z * Fr[1] + c0.w * Fr[2];
            g_h[(size_t)SO + base] = __float2half(h);                    // t=1
#pragma unroll
            for (int j = 1; j <= 30; j++) {                              // steps 1..30
                float4 cc = Cs[j * NO + o];
                h = fmaf(cc.x, h, fmaf(cc.y, Fr[2 * j + 1], cc.z * Fr[2 * j + 2]));
                g_h[(size_t)(j + 1) * SO + base] = __float2half(h);      // t=2..31
            }
        } else {
            float4 c0 = Cs[o];                                           // step 32m-1
            h = fmaf(c0.x, h, fmaf(c0.y, carry, c0.z * Fr[0]));
            g_h[(size_t)(SPC * m) * SO + base] = __float2half(h);        // t=32m
#pragma unroll
            for (int j = 1; j <= 31; j++) {                              // steps 32m-1+j
                float4 cc = Cs[j * NO + o];
                h = fmaf(cc.x, h, fmaf(cc.y, Fr[2 * j - 1], cc.z * Fr[2 * j]));
                g_h[(size_t)(SPC * m + j) * SO + base] = __float2half(h);
            }
        }
        carry = Fr[CT - 1];
        __syncthreads();
    }
    // after m=31: steps 0..1022 done, carry = f[2047]
    g_fc[base] = carry;
}

// ---------------------------------------------------------------------------
// Kernel 4: stats. One block per t; thread = (o-quad, s-slice). Single-pass
// shifted-moments mean/var (shift = h[s=0]+nr/2, exact algebra), float4 u
// loads + half4 h loads. Tail t reconstructs h from (alpha,beta,f_c), L2-hot.
// ---------------------------------------------------------------------------
__global__ void __launch_bounds__(256) stats(const float* __restrict__ u,
                                             float* __restrict__ out) {
    __shared__ float4 R0[16][16], R1[16][16], R2[16][16];

    int t   = blockIdx.x;
    int tid = threadIdx.x;
    int q   = tid & 15;                   // o-quad: o = 4q..4q+3
    int ss  = tid >> 4;                   // s-slice 0..15

    bool tail = (t >= HALF_T);
    float4 nr4 = *(const float4*)&g_nr[q * 4];
    float4 al = make_float4(1.f, 1.f, 1.f, 1.f);
    float4 be = make_float4(0.f, 0.f, 0.f, 0.f);
    if (tail) {
        al = *(const float4*)&g_alpha[(t - HALF_T) * NO + q * 4];
        be = *(const float4*)&g_beta [(t - HALF_T) * NO + q * 4];
    }
    const __half* hrow = g_h + (size_t)(tail ? (HALF_T - 1) : t) * SO;
    const float*  urow = u + (size_t)t * SO;

    // shift per (t, o): sample s=0 value + nr/2 (~= noisy mean; exact algebra)
    float4 h0;
    {
        uint2 hb = *(const uint2*)(hrow + q * 4);
        __half2 p0 = *reinterpret_cast<const __half2*>(&hb.x);
        __half2 p1 = *reinterpret_cast<const __half2*>(&hb.y);
        float2 f0 = __half22float2(p0), f1 = __half22float2(p1);
        h0 = make_float4(f0.x, f0.y, f1.x, f1.y);
    }
    if (tail) {
        float4 fc0 = *(const float4*)&g_fc[q * 4];
        h0.x = fmaf(al.x, h0.x, be.x * fc0.x);
        h0.y = fmaf(al.y, h0.y, be.y * fc0.y);
        h0.z = fmaf(al.z, h0.z, be.z * fc0.z);
        h0.w = fmaf(al.w, h0.w, be.w * fc0.w);
    }
    float4 shift = make_float4(fmaf(nr4.x, 0.5f, h0.x), fmaf(nr4.y, 0.5f, h0.y),
                               fmaf(nr4.z, 0.5f, h0.z), fmaf(nr4.w, 0.5f, h0.w));

    float4 sh = make_float4(0.f, 0.f, 0.f, 0.f);
    float4 sd = sh, sq = sh;
#pragma unroll 4
    for (int i = 0; i < 32; i++) {
        int idx = (i * 16 + ss) * NO + q * 4;
        uint2 hb = *(const uint2*)(hrow + idx);
        __half2 p0 = *reinterpret_cast<const __half2*>(&hb.x);
        __half2 p1 = *reinterpret_cast<const __half2*>(&hb.y);
        float2 f0 = __half22float2(p0), f1 = __half22float2(p1);
        float4 hv = make_float4(f0.x, f0.y, f1.x, f1.y);
        if (tail) {
            float4 fc = *(const float4*)&g_fc[idx];
            hv.x = fmaf(al.x, hv.x, be.x * fc.x);
            hv.y = fmaf(al.y, hv.y, be.y * fc.y);
            hv.z = fmaf(al.z, hv.z, be.z * fc.z);
            hv.w = fmaf(al.w, hv.w, be.w * fc.w);
        }
        float4 uv = *(const float4*)&urow[idx];
        float4 d = make_float4(fmaf(nr4.x, uv.x, hv.x) - shift.x,
                               fmaf(nr4.y, uv.y, hv.y) - shift.y,
                               fmaf(nr4.z, uv.z, hv.z) - shift.z,
                               fmaf(nr4.w, uv.w, hv.w) - shift.w);
        sh.x += hv.x; sh.y += hv.y; sh.z += hv.z; sh.w += hv.w;
        sd.x += d.x;  sd.y += d.y;  sd.z += d.z;  sd.w += d.w;
        sq.x = fmaf(d.x, d.x, sq.x); sq.y = fmaf(d.y, d.y, sq.y);
        sq.z = fmaf(d.z, d.z, sq.z); sq.w = fmaf(d.w, d.w, sq.w);
    }
    R0[ss][q] = sh; R1[ss][q] = sd; R2[ss][q] = sq;
    __syncthreads();
    if (tid < 16) {
        float4 Sh = make_float4(0.f, 0.f, 0.f, 0.f);
        float4 Sd = Sh, Sq = Sh;
#pragma unroll
        for (int j = 0; j < 16; j++) {
            float4 a0 = R0[j][tid], a1 = R1[j][tid], a2 = R2[j][tid];
            Sh.x += a0.x; Sh.y += a0.y; Sh.z += a0.z; Sh.w += a0.w;
            Sd.x += a1.x; Sd.y += a1.y; Sd.z += a1.z; Sd.w += a1.w;
            Sq.x += a2.x; Sq.y += a2.y; Sq.z += a2.z; Sq.w += a2.w;
        }
        const float i512 = 1.0f / 512.0f, i511 = 1.0f / 511.0f;
        float4 mean = make_float4(Sh.x * i512, Sh.y * i512, Sh.z * i512, Sh.w * i512);
        float4 var  = make_float4((Sq.x - Sd.x * Sd.x * i512) * i511 + 1e-6f,
                                  (Sq.y - Sd.y * Sd.y * i512) * i511 + 1e-6f,
                                  (Sq.z - Sd.z * Sd.z * i512) * i511 + 1e-6f,
                                  (Sq.w - Sd.w * Sd.w * i512) * i511 + 1e-6f);
        *(float4*)&out[t * NO + tid * 4]           = mean;   // [0,t,o]
        *(float4*)&out[NT * NO + t * NO + tid * 4] = var;    // [1,t,o]
    }
}

// ---------------------------------------------------------------------------
// Launch
// ---------------------------------------------------------------------------
extern "C" void kernel_launch(void* const* d_in, const int* in_sizes, int n_in,
                              void* d_out, int out_size) {
    const float* t_  = (const float*)d_in[0];   // [T]
    const float* f_  = (const float*)d_in[1];   // [S,O,T]
    const float* ra_ = (const float*)d_in[2];   // [O,1]
    const float* rb_ = (const float*)d_in[3];
    const float* rc_ = (const float*)d_in[4];
    const float* rn_ = (const float*)d_in[5];
    const float* u_  = (const float*)d_in[6];   // [T,S,O]
    float* out = (float*)d_out;                 // [2,T,O]

    cudaFuncSetAttribute(chains, cudaFuncAttributeMaxDynamicSharedMemorySize,
                         CH_SMEM);

    coefA<<<2047, NO>>>(t_, ra_, rb_, rc_, rn_);
    coefB<<<NO, 64>>>();
    chains<<<NS / SPB, 256, CH_SMEM>>>(f_);
    stats<<<NT, 256>>>(u_, out);
}